// round 1
// baseline (speedup 1.0000x reference)
#include <cuda_runtime.h>

#define FEA 128      // ATOM_FEA
#define NBF 64       // NBR_FEA
#define OUTD 256     // 2*FEA
#define INDIM 320    // 2*FEA + NBF

#define MAXN 50000
#define MAXE 600000

// ---------------- device scratch (no runtime allocation allowed) ----------------
__device__ float  g_P[(size_t)MAXN * OUTD];   // X @ W[:, 0:128]^T     (gathered by nbr)
__device__ float  g_Q[(size_t)MAXN * OUTD];   // X @ W[:, 128:256]^T   (gathered by src)
__device__ float  g_U[(size_t)MAXE * OUTD];   // gated pre-BN, per edge
__device__ float  g_S[(size_t)MAXN * FEA];    // neighbor-summed messages pre-BN2
__device__ double g_s1[OUTD], g_s2[OUTD];     // BN1 sum / sumsq
__device__ double g_t1[FEA],  g_t2[FEA];      // BN2 sum / sumsq
__device__ float  g_bn1s[OUTD], g_bn1h[OUTD]; // BN1 scale/shift
__device__ float  g_bn2s[FEA],  g_bn2h[FEA];  // BN2 scale/shift
__device__ int    g_is64;

__device__ __forceinline__ long ldidx(const void* p, long i, int is64) {
    return is64 ? (long)((const long long*)p)[i] : (long)((const int*)p)[i];
}
__device__ __forceinline__ float softplusf(float z) {
    return fmaxf(z, 0.0f) + log1pf(__expf(-fabsf(z)));
}
__device__ __forceinline__ float sigmoidf(float z) {
    return 1.0f / (1.0f + __expf(-z));
}

// ---------------- kernel 0: zero stats + detect index dtype ----------------
__global__ void k_init(const int* __restrict__ ei32) {
    int t = threadIdx.x;
    for (int i = t; i < OUTD; i += 256) { g_s1[i] = 0.0; g_s2[i] = 0.0; }
    for (int i = t; i < FEA;  i += 256) { g_t1[i] = 0.0; g_t2[i] = 0.0; }
    // src row = repeat(arange(N), 12). Under int64 little-endian, 32-bit word 12
    // is the high half of src[6] == 0. Under int32, word 12 is src[12] == 1.
    if (t == 0) g_is64 = (ei32[12] == 0) ? 1 : 0;
}

// ---------------- kernel 1: node GEMM  (P | Q) = X @ [W1 | W2]^T ----------------
// C[r][c] for c in [0,512): c<256 -> P[r][c] = sum_k x[r][k]*W[c][k]
//                           c>=256-> Q[r][c-256] = sum_k x[r][k]*W[c-256][128+k]
#define BM 128
#define BN 128
#define BK 32

__global__ __launch_bounds__(256, 2)
void k_nodegemm(const float* __restrict__ x, const float* __restrict__ W, int n_nodes) {
    __shared__ float sA[BK][BM + 4];   // x^T tile
    __shared__ float sB[BK][BN];       // W^T tile
    int t  = threadIdx.x;
    int tx = t & 15, ty = t >> 4;
    int rBase = blockIdx.x * BM;
    int cBase = blockIdx.y * BN;       // 0,128 -> P ; 256,384 -> Q
    float acc[8][8] = {};

    for (int k0 = 0; k0 < FEA; k0 += BK) {
        #pragma unroll
        for (int l = 0; l < 4; l++) {
            int i = t + l * 256;          // 0..1023, 8 float4 per row
            int r  = i >> 3;
            int kk = (i & 7) << 2;
            float4 v = make_float4(0.f, 0.f, 0.f, 0.f);
            int gr = rBase + r;
            if (gr < n_nodes) v = *(const float4*)(x + (size_t)gr * FEA + k0 + kk);
            sA[kk+0][r] = v.x; sA[kk+1][r] = v.y; sA[kk+2][r] = v.z; sA[kk+3][r] = v.w;
        }
        #pragma unroll
        for (int l = 0; l < 4; l++) {
            int i = t + l * 256;
            int c  = i >> 3;
            int kk = (i & 7) << 2;
            int gc = cBase + c;
            int row  = gc & 255;
            int koff = ((gc >= 256) ? FEA : 0) + k0 + kk;
            float4 v = *(const float4*)(W + (size_t)row * INDIM + koff);
            sB[kk+0][c] = v.x; sB[kk+1][c] = v.y; sB[kk+2][c] = v.z; sB[kk+3][c] = v.w;
        }
        __syncthreads();
        #pragma unroll
        for (int k = 0; k < BK; k++) {
            float a[8], bb[8];
            *(float4*)&a[0]  = *(const float4*)&sA[k][ty*8];
            *(float4*)&a[4]  = *(const float4*)&sA[k][ty*8 + 4];
            *(float4*)&bb[0] = *(const float4*)&sB[k][tx*4];
            *(float4*)&bb[4] = *(const float4*)&sB[k][tx*4 + 64];
            #pragma unroll
            for (int i = 0; i < 8; i++)
                #pragma unroll
                for (int j = 0; j < 8; j++)
                    acc[i][j] = fmaf(a[i], bb[j], acc[i][j]);
        }
        __syncthreads();
    }

    int c0 = cBase + tx * 4;
    #pragma unroll
    for (int i = 0; i < 8; i++) {
        int r = rBase + ty * 8 + i;
        if (r >= n_nodes) break;
        float4 v0 = make_float4(acc[i][0], acc[i][1], acc[i][2], acc[i][3]);
        float4 v1 = make_float4(acc[i][4], acc[i][5], acc[i][6], acc[i][7]);
        if (c0 < OUTD) {
            *(float4*)(g_P + (size_t)r * OUTD + c0)      = v0;
            *(float4*)(g_P + (size_t)r * OUTD + c0 + 64) = v1;
        } else {
            *(float4*)(g_Q + (size_t)r * OUTD + (c0 - OUTD))      = v0;
            *(float4*)(g_Q + (size_t)r * OUTD + (c0 - OUTD) + 64) = v1;
        }
    }
}

// ---------------- kernel 2: edge GEMM + gather + U store + BN1 sums ----------------
#define EBM 128
#define EBN 128
#define EBK 32

__global__ __launch_bounds__(256, 2)
void k_edgegemm(const float* __restrict__ ea, const float* __restrict__ W,
                const float* __restrict__ bias, const void* __restrict__ eidx,
                long n_edges) {
    __shared__ float sA[EBK][EBM + 4];
    __shared__ float sB[EBK][EBN];
    int t  = threadIdx.x;
    int tx = t & 15, ty = t >> 4;
    long eBase = (long)blockIdx.x * EBM;
    int  cBase = blockIdx.y * EBN;
    int  is64  = g_is64;
    float acc[8][8] = {};

    for (int k0 = 0; k0 < NBF; k0 += EBK) {
        #pragma unroll
        for (int l = 0; l < 4; l++) {
            int i = t + l * 256;
            int r  = i >> 3;
            int kk = (i & 7) << 2;
            float4 v = make_float4(0.f, 0.f, 0.f, 0.f);
            long ge = eBase + r;
            if (ge < n_edges) v = *(const float4*)(ea + ge * NBF + k0 + kk);
            sA[kk+0][r] = v.x; sA[kk+1][r] = v.y; sA[kk+2][r] = v.z; sA[kk+3][r] = v.w;
        }
        #pragma unroll
        for (int l = 0; l < 4; l++) {
            int i = t + l * 256;
            int c  = i >> 3;
            int kk = (i & 7) << 2;
            int gc = cBase + c;
            float4 v = *(const float4*)(W + (size_t)gc * INDIM + 2*FEA + k0 + kk);
            sB[kk+0][c] = v.x; sB[kk+1][c] = v.y; sB[kk+2][c] = v.z; sB[kk+3][c] = v.w;
        }
        __syncthreads();
        #pragma unroll
        for (int k = 0; k < EBK; k++) {
            float a[8], bb[8];
            *(float4*)&a[0]  = *(const float4*)&sA[k][ty*8];
            *(float4*)&a[4]  = *(const float4*)&sA[k][ty*8 + 4];
            *(float4*)&bb[0] = *(const float4*)&sB[k][tx*4];
            *(float4*)&bb[4] = *(const float4*)&sB[k][tx*4 + 64];
            #pragma unroll
            for (int i = 0; i < 8; i++)
                #pragma unroll
                for (int j = 0; j < 8; j++)
                    acc[i][j] = fmaf(a[i], bb[j], acc[i][j]);
        }
        __syncthreads();
    }

    // epilogue: u = acc + b[c] + P[nbr][c] + Q[src][c]; store U; partial BN1 sums
    float ps[8] = {}, ps2[8] = {};
    int c0 = cBase + tx * 4;
    float4 bv0 = *(const float4*)(bias + c0);
    float4 bv1 = *(const float4*)(bias + c0 + 64);
    #pragma unroll
    for (int i = 0; i < 8; i++) {
        long e = eBase + ty * 8 + i;
        if (e >= n_edges) break;
        long nb = ldidx(eidx, n_edges + e, is64);
        long sr = ldidx(eidx, e, is64);
        const float* Pr = g_P + (size_t)nb * OUTD;
        const float* Qr = g_Q + (size_t)sr * OUTD;
        float4 p0 = *(const float4*)(Pr + c0);
        float4 p1 = *(const float4*)(Pr + c0 + 64);
        float4 q0 = *(const float4*)(Qr + c0);
        float4 q1 = *(const float4*)(Qr + c0 + 64);
        float u[8];
        u[0] = acc[i][0] + bv0.x + p0.x + q0.x;
        u[1] = acc[i][1] + bv0.y + p0.y + q0.y;
        u[2] = acc[i][2] + bv0.z + p0.z + q0.z;
        u[3] = acc[i][3] + bv0.w + p0.w + q0.w;
        u[4] = acc[i][4] + bv1.x + p1.x + q1.x;
        u[5] = acc[i][5] + bv1.y + p1.y + q1.y;
        u[6] = acc[i][6] + bv1.z + p1.z + q1.z;
        u[7] = acc[i][7] + bv1.w + p1.w + q1.w;
        *(float4*)(g_U + (size_t)e * OUTD + c0)      = make_float4(u[0], u[1], u[2], u[3]);
        *(float4*)(g_U + (size_t)e * OUTD + c0 + 64) = make_float4(u[4], u[5], u[6], u[7]);
        #pragma unroll
        for (int j = 0; j < 8; j++) { ps[j] += u[j]; ps2[j] += u[j] * u[j]; }
    }

    // block reduce 16 ty-rows -> per-channel partial, one double atomic per channel
    __syncthreads();
    float* sred = &sA[0][0];   // 16*128 floats, fits in sA
    #pragma unroll
    for (int j = 0; j < 8; j++) {
        int cl = (j < 4) ? (tx * 4 + j) : (tx * 4 + 64 + (j - 4));
        sred[ty * 128 + cl] = ps[j];
    }
    __syncthreads();
    if (t < 128) {
        float s = 0.f;
        #pragma unroll
        for (int w = 0; w < 16; w++) s += sred[w * 128 + t];
        atomicAdd(&g_s1[cBase + t], (double)s);
    }
    __syncthreads();
    #pragma unroll
    for (int j = 0; j < 8; j++) {
        int cl = (j < 4) ? (tx * 4 + j) : (tx * 4 + 64 + (j - 4));
        sred[ty * 128 + cl] = ps2[j];
    }
    __syncthreads();
    if (t < 128) {
        float s = 0.f;
        #pragma unroll
        for (int w = 0; w < 16; w++) s += sred[w * 128 + t];
        atomicAdd(&g_s2[cBase + t], (double)s);
    }
}

// ---------------- kernel 3: BN1 finalize ----------------
__global__ void k_bn1fin(const float* __restrict__ g1, const float* __restrict__ b1,
                         long n_edges) {
    int t = threadIdx.x;  // 256
    double inv = 1.0 / (double)n_edges;
    double m   = g_s1[t] * inv;
    double var = g_s2[t] * inv - m * m;
    float rs = (float)rsqrt(var + 1e-5);
    float sc = g1[t] * rs;
    g_bn1s[t] = sc;
    g_bn1h[t] = b1[t] - (float)m * sc;
}

// ---------------- kernel 4: gate+softplus, 12-neighbor sum, BN2 sums ----------------
#define NPB 32
__global__ __launch_bounds__(128)
void k_msg(int n_nodes, int num_nbr) {
    int tx = threadIdx.x;  // channel 0..127
    float s1f = g_bn1s[tx],       h1f = g_bn1h[tx];
    float s1c = g_bn1s[128 + tx], h1c = g_bn1h[128 + tx];
    float tsum = 0.f, tsq = 0.f;
    int n0 = blockIdx.x * NPB;
    for (int nn = 0; nn < NPB; nn++) {
        int node = n0 + nn;
        if (node >= n_nodes) break;
        float s = 0.f;
        long eb = (long)node * num_nbr;
        for (int j = 0; j < num_nbr; j++) {
            const float* Ur = g_U + (size_t)(eb + j) * OUTD;
            float fz = fmaf(s1f, Ur[tx],       h1f);
            float cz = fmaf(s1c, Ur[128 + tx], h1c);
            s += sigmoidf(fz) * softplusf(cz);
        }
        g_S[(size_t)node * FEA + tx] = s;
        tsum += s; tsq += s * s;
    }
    atomicAdd(&g_t1[tx], (double)tsum);
    atomicAdd(&g_t2[tx], (double)tsq);
}

// ---------------- kernel 5: BN2 finalize ----------------
__global__ void k_bn2fin(const float* __restrict__ g2, const float* __restrict__ b2,
                         int n_nodes) {
    int t = threadIdx.x;  // 128
    double inv = 1.0 / (double)n_nodes;
    double m   = g_t1[t] * inv;
    double var = g_t2[t] * inv - m * m;
    float rs = (float)rsqrt(var + 1e-5);
    float sc = g2[t] * rs;
    g_bn2s[t] = sc;
    g_bn2h[t] = b2[t] - (float)m * sc;
}

// ---------------- kernel 6: output = softplus(x + bn2(S)) ----------------
__global__ void k_out(const float* __restrict__ x, float* __restrict__ out, long total) {
    long i = (long)blockIdx.x * blockDim.x + threadIdx.x;
    if (i >= total) return;
    int c = (int)(i & (FEA - 1));
    float v = x[i] + g_bn2s[c] * g_S[i] + g_bn2h[c];
    out[i] = softplusf(v);
}

// ---------------- launch ----------------
extern "C" void kernel_launch(void* const* d_in, const int* in_sizes, int n_in,
                              void* d_out, int out_size) {
    const float* x    = (const float*)d_in[0];
    const void*  eidx = d_in[1];
    const float* ea   = (const float*)d_in[2];
    const float* W    = (const float*)d_in[3];
    const float* b    = (const float*)d_in[4];
    const float* g1   = (const float*)d_in[5];
    const float* b1   = (const float*)d_in[6];
    const float* g2   = (const float*)d_in[7];
    const float* b2   = (const float*)d_in[8];
    float* out = (float*)d_out;

    int  n_nodes = in_sizes[0] / FEA;
    long n_edges = (long)in_sizes[2] / NBF;
    int  num_nbr = (int)(n_edges / n_nodes);

    k_init<<<1, 256>>>((const int*)eidx);

    dim3 grid1((n_nodes + BM - 1) / BM, 4);
    k_nodegemm<<<grid1, 256>>>(x, W, n_nodes);

    dim3 grid2((unsigned)((n_edges + EBM - 1) / EBM), 2);
    k_edgegemm<<<grid2, 256>>>(ea, W, b, eidx, n_edges);

    k_bn1fin<<<1, 256>>>(g1, b1, n_edges);

    k_msg<<<(n_nodes + NPB - 1) / NPB, 128>>>(n_nodes, num_nbr);

    k_bn2fin<<<1, 128>>>(g2, b2, n_nodes);

    long total = (long)n_nodes * FEA;
    k_out<<<(unsigned)((total + 255) / 256), 256>>>(x, out, total);
}

// round 2
// speedup vs baseline: 1.0013x; 1.0013x over previous
#include <cuda_runtime.h>

#define FEA 128      // ATOM_FEA
#define NBF 64       // NBR_FEA
#define OUTD 256     // 2*FEA
#define INDIM 320    // 2*FEA + NBF

#define MAXN 50000
#define MAXE 600000

// ---------------- device scratch (no runtime allocation allowed) ----------------
__device__ float  g_P[(size_t)MAXN * OUTD];   // X @ W[:, 0:128]^T     (gathered by nbr)
__device__ float  g_Q[(size_t)MAXN * OUTD];   // X @ W[:, 128:256]^T   (gathered by src)
__device__ float  g_U[(size_t)MAXE * OUTD];   // gated pre-BN, per edge
__device__ float  g_S[(size_t)MAXN * FEA];    // neighbor-summed messages pre-BN2
__device__ double g_s1[OUTD], g_s2[OUTD];     // BN1 sum / sumsq
__device__ double g_t1[FEA],  g_t2[FEA];      // BN2 sum / sumsq
__device__ float  g_bn1s[OUTD], g_bn1h[OUTD]; // BN1 scale/shift
__device__ float  g_bn2s[FEA],  g_bn2h[FEA];  // BN2 scale/shift
__device__ int    g_is64;

__device__ __forceinline__ long ldidx(const void* p, long i, int is64) {
    return is64 ? (long)((const long long*)p)[i] : (long)((const int*)p)[i];
}
__device__ __forceinline__ float softplusf(float z) {
    return fmaxf(z, 0.0f) + log1pf(__expf(-fabsf(z)));
}
__device__ __forceinline__ float sigmoidf(float z) {
    return 1.0f / (1.0f + __expf(-z));
}

// ---------------- kernel 0: zero stats + detect index dtype ----------------
__global__ void k_init(const int* __restrict__ ei32) {
    int t = threadIdx.x;
    for (int i = t; i < OUTD; i += 256) { g_s1[i] = 0.0; g_s2[i] = 0.0; }
    for (int i = t; i < FEA;  i += 256) { g_t1[i] = 0.0; g_t2[i] = 0.0; }
    // src row = repeat(arange(N), 12). Under int64 little-endian, 32-bit word 12
    // is the high half of src[6] == 0. Under int32, word 12 is src[12] == 1.
    if (t == 0) g_is64 = (ei32[12] == 0) ? 1 : 0;
}

// ---------------- kernel 1: node GEMM  (P | Q) = X @ [W1 | W2]^T ----------------
// C[r][c] for c in [0,512): c<256 -> P[r][c] = sum_k x[r][k]*W[c][k]
//                           c>=256-> Q[r][c-256] = sum_k x[r][k]*W[c-256][128+k]
#define BM 128
#define BN 128
#define BK 32

__global__ __launch_bounds__(256, 2)
void k_nodegemm(const float* __restrict__ x, const float* __restrict__ W, int n_nodes) {
    __shared__ float sA[BK][BM + 4];   // x^T tile
    __shared__ float sB[BK][BN];       // W^T tile
    int t  = threadIdx.x;
    int tx = t & 15, ty = t >> 4;
    int rBase = blockIdx.x * BM;
    int cBase = blockIdx.y * BN;       // 0,128 -> P ; 256,384 -> Q
    float acc[8][8] = {};

    for (int k0 = 0; k0 < FEA; k0 += BK) {
        #pragma unroll
        for (int l = 0; l < 4; l++) {
            int i = t + l * 256;          // 0..1023, 8 float4 per row
            int r  = i >> 3;
            int kk = (i & 7) << 2;
            float4 v = make_float4(0.f, 0.f, 0.f, 0.f);
            int gr = rBase + r;
            if (gr < n_nodes) v = *(const float4*)(x + (size_t)gr * FEA + k0 + kk);
            sA[kk+0][r] = v.x; sA[kk+1][r] = v.y; sA[kk+2][r] = v.z; sA[kk+3][r] = v.w;
        }
        #pragma unroll
        for (int l = 0; l < 4; l++) {
            int i = t + l * 256;
            int c  = i >> 3;
            int kk = (i & 7) << 2;
            int gc = cBase + c;
            int row  = gc & 255;
            int koff = ((gc >= 256) ? FEA : 0) + k0 + kk;
            float4 v = *(const float4*)(W + (size_t)row * INDIM + koff);
            sB[kk+0][c] = v.x; sB[kk+1][c] = v.y; sB[kk+2][c] = v.z; sB[kk+3][c] = v.w;
        }
        __syncthreads();
        #pragma unroll
        for (int k = 0; k < BK; k++) {
            float a[8], bb[8];
            *(float4*)&a[0]  = *(const float4*)&sA[k][ty*8];
            *(float4*)&a[4]  = *(const float4*)&sA[k][ty*8 + 4];
            *(float4*)&bb[0] = *(const float4*)&sB[k][tx*4];
            *(float4*)&bb[4] = *(const float4*)&sB[k][tx*4 + 64];
            #pragma unroll
            for (int i = 0; i < 8; i++)
                #pragma unroll
                for (int j = 0; j < 8; j++)
                    acc[i][j] = fmaf(a[i], bb[j], acc[i][j]);
        }
        __syncthreads();
    }

    int c0 = cBase + tx * 4;
    #pragma unroll
    for (int i = 0; i < 8; i++) {
        int r = rBase + ty * 8 + i;
        if (r >= n_nodes) break;
        float4 v0 = make_float4(acc[i][0], acc[i][1], acc[i][2], acc[i][3]);
        float4 v1 = make_float4(acc[i][4], acc[i][5], acc[i][6], acc[i][7]);
        if (c0 < OUTD) {
            *(float4*)(g_P + (size_t)r * OUTD + c0)      = v0;
            *(float4*)(g_P + (size_t)r * OUTD + c0 + 64) = v1;
        } else {
            *(float4*)(g_Q + (size_t)r * OUTD + (c0 - OUTD))      = v0;
            *(float4*)(g_Q + (size_t)r * OUTD + (c0 - OUTD) + 64) = v1;
        }
    }
}

// ---------------- kernel 2: edge GEMM + gather + U store + BN1 sums ----------------
#define EBM 128
#define EBN 128
#define EBK 32

__global__ __launch_bounds__(256, 2)
void k_edgegemm(const float* __restrict__ ea, const float* __restrict__ W,
                const float* __restrict__ bias, const void* __restrict__ eidx,
                long n_edges) {
    __shared__ float sA[EBK][EBM + 4];
    __shared__ float sB[EBK][EBN];
    int t  = threadIdx.x;
    int tx = t & 15, ty = t >> 4;
    long eBase = (long)blockIdx.x * EBM;
    int  cBase = blockIdx.y * EBN;
    int  is64  = g_is64;
    float acc[8][8] = {};

    for (int k0 = 0; k0 < NBF; k0 += EBK) {
        #pragma unroll
        for (int l = 0; l < 4; l++) {
            int i = t + l * 256;
            int r  = i >> 3;
            int kk = (i & 7) << 2;
            float4 v = make_float4(0.f, 0.f, 0.f, 0.f);
            long ge = eBase + r;
            if (ge < n_edges) v = *(const float4*)(ea + ge * NBF + k0 + kk);
            sA[kk+0][r] = v.x; sA[kk+1][r] = v.y; sA[kk+2][r] = v.z; sA[kk+3][r] = v.w;
        }
        #pragma unroll
        for (int l = 0; l < 4; l++) {
            int i = t + l * 256;
            int c  = i >> 3;
            int kk = (i & 7) << 2;
            int gc = cBase + c;
            float4 v = *(const float4*)(W + (size_t)gc * INDIM + 2*FEA + k0 + kk);
            sB[kk+0][c] = v.x; sB[kk+1][c] = v.y; sB[kk+2][c] = v.z; sB[kk+3][c] = v.w;
        }
        __syncthreads();
        #pragma unroll
        for (int k = 0; k < EBK; k++) {
            float a[8], bb[8];
            *(float4*)&a[0]  = *(const float4*)&sA[k][ty*8];
            *(float4*)&a[4]  = *(const float4*)&sA[k][ty*8 + 4];
            *(float4*)&bb[0] = *(const float4*)&sB[k][tx*4];
            *(float4*)&bb[4] = *(const float4*)&sB[k][tx*4 + 64];
            #pragma unroll
            for (int i = 0; i < 8; i++)
                #pragma unroll
                for (int j = 0; j < 8; j++)
                    acc[i][j] = fmaf(a[i], bb[j], acc[i][j]);
        }
        __syncthreads();
    }

    // epilogue: u = acc + b[c] + P[nbr][c] + Q[src][c]; store U; partial BN1 sums
    float ps[8] = {}, ps2[8] = {};
    int c0 = cBase + tx * 4;
    float4 bv0 = *(const float4*)(bias + c0);
    float4 bv1 = *(const float4*)(bias + c0 + 64);
    #pragma unroll
    for (int i = 0; i < 8; i++) {
        long e = eBase + ty * 8 + i;
        if (e >= n_edges) break;
        long nb = ldidx(eidx, n_edges + e, is64);
        long sr = ldidx(eidx, e, is64);
        const float* Pr = g_P + (size_t)nb * OUTD;
        const float* Qr = g_Q + (size_t)sr * OUTD;
        float4 p0 = *(const float4*)(Pr + c0);
        float4 p1 = *(const float4*)(Pr + c0 + 64);
        float4 q0 = *(const float4*)(Qr + c0);
        float4 q1 = *(const float4*)(Qr + c0 + 64);
        float u[8];
        u[0] = acc[i][0] + bv0.x + p0.x + q0.x;
        u[1] = acc[i][1] + bv0.y + p0.y + q0.y;
        u[2] = acc[i][2] + bv0.z + p0.z + q0.z;
        u[3] = acc[i][3] + bv0.w + p0.w + q0.w;
        u[4] = acc[i][4] + bv1.x + p1.x + q1.x;
        u[5] = acc[i][5] + bv1.y + p1.y + q1.y;
        u[6] = acc[i][6] + bv1.z + p1.z + q1.z;
        u[7] = acc[i][7] + bv1.w + p1.w + q1.w;
        *(float4*)(g_U + (size_t)e * OUTD + c0)      = make_float4(u[0], u[1], u[2], u[3]);
        *(float4*)(g_U + (size_t)e * OUTD + c0 + 64) = make_float4(u[4], u[5], u[6], u[7]);
        #pragma unroll
        for (int j = 0; j < 8; j++) { ps[j] += u[j]; ps2[j] += u[j] * u[j]; }
    }

    // block reduce 16 ty-rows -> per-channel partial, one double atomic per channel
    __syncthreads();
    float* sred = &sA[0][0];   // 16*128 floats, fits in sA
    #pragma unroll
    for (int j = 0; j < 8; j++) {
        int cl = (j < 4) ? (tx * 4 + j) : (tx * 4 + 64 + (j - 4));
        sred[ty * 128 + cl] = ps[j];
    }
    __syncthreads();
    if (t < 128) {
        float s = 0.f;
        #pragma unroll
        for (int w = 0; w < 16; w++) s += sred[w * 128 + t];
        atomicAdd(&g_s1[cBase + t], (double)s);
    }
    __syncthreads();
    #pragma unroll
    for (int j = 0; j < 8; j++) {
        int cl = (j < 4) ? (tx * 4 + j) : (tx * 4 + 64 + (j - 4));
        sred[ty * 128 + cl] = ps2[j];
    }
    __syncthreads();
    if (t < 128) {
        float s = 0.f;
        #pragma unroll
        for (int w = 0; w < 16; w++) s += sred[w * 128 + t];
        atomicAdd(&g_s2[cBase + t], (double)s);
    }
}

// ---------------- kernel 3: BN1 finalize ----------------
__global__ void k_bn1fin(const float* __restrict__ g1, const float* __restrict__ b1,
                         long n_edges) {
    int t = threadIdx.x;  // 256
    double inv = 1.0 / (double)n_edges;
    double m   = g_s1[t] * inv;
    double var = g_s2[t] * inv - m * m;
    float rs = (float)rsqrt(var + 1e-5);
    float sc = g1[t] * rs;
    g_bn1s[t] = sc;
    g_bn1h[t] = b1[t] - (float)m * sc;
}

// ---------------- kernel 4: gate+softplus, 12-neighbor sum, BN2 sums ----------------
#define NPB 32
__global__ __launch_bounds__(128)
void k_msg(int n_nodes, int num_nbr) {
    int tx = threadIdx.x;  // channel 0..127
    float s1f = g_bn1s[tx],       h1f = g_bn1h[tx];
    float s1c = g_bn1s[128 + tx], h1c = g_bn1h[128 + tx];
    float tsum = 0.f, tsq = 0.f;
    int n0 = blockIdx.x * NPB;
    for (int nn = 0; nn < NPB; nn++) {
        int node = n0 + nn;
        if (node >= n_nodes) break;
        float s = 0.f;
        long eb = (long)node * num_nbr;
        for (int j = 0; j < num_nbr; j++) {
            const float* Ur = g_U + (size_t)(eb + j) * OUTD;
            float fz = fmaf(s1f, Ur[tx],       h1f);
            float cz = fmaf(s1c, Ur[128 + tx], h1c);
            s += sigmoidf(fz) * softplusf(cz);
        }
        g_S[(size_t)node * FEA + tx] = s;
        tsum += s; tsq += s * s;
    }
    atomicAdd(&g_t1[tx], (double)tsum);
    atomicAdd(&g_t2[tx], (double)tsq);
}

// ---------------- kernel 5: BN2 finalize ----------------
__global__ void k_bn2fin(const float* __restrict__ g2, const float* __restrict__ b2,
                         int n_nodes) {
    int t = threadIdx.x;  // 128
    double inv = 1.0 / (double)n_nodes;
    double m   = g_t1[t] * inv;
    double var = g_t2[t] * inv - m * m;
    float rs = (float)rsqrt(var + 1e-5);
    float sc = g2[t] * rs;
    g_bn2s[t] = sc;
    g_bn2h[t] = b2[t] - (float)m * sc;
}

// ---------------- kernel 6: output = softplus(x + bn2(S)) ----------------
__global__ void k_out(const float* __restrict__ x, float* __restrict__ out, long total) {
    long i = (long)blockIdx.x * blockDim.x + threadIdx.x;
    if (i >= total) return;
    int c = (int)(i & (FEA - 1));
    float v = x[i] + g_bn2s[c] * g_S[i] + g_bn2h[c];
    out[i] = softplusf(v);
}

// ---------------- launch ----------------
extern "C" void kernel_launch(void* const* d_in, const int* in_sizes, int n_in,
                              void* d_out, int out_size) {
    const float* x    = (const float*)d_in[0];
    const void*  eidx = d_in[1];
    const float* ea   = (const float*)d_in[2];
    const float* W    = (const float*)d_in[3];
    const float* b    = (const float*)d_in[4];
    const float* g1   = (const float*)d_in[5];
    const float* b1   = (const float*)d_in[6];
    const float* g2   = (const float*)d_in[7];
    const float* b2   = (const float*)d_in[8];
    float* out = (float*)d_out;

    int  n_nodes = in_sizes[0] / FEA;
    long n_edges = (long)in_sizes[2] / NBF;
    int  num_nbr = (int)(n_edges / n_nodes);

    k_init<<<1, 256>>>((const int*)eidx);

    dim3 grid1((n_nodes + BM - 1) / BM, 4);
    k_nodegemm<<<grid1, 256>>>(x, W, n_nodes);

    dim3 grid2((unsigned)((n_edges + EBM - 1) / EBM), 2);
    k_edgegemm<<<grid2, 256>>>(ea, W, b, eidx, n_edges);

    k_bn1fin<<<1, 256>>>(g1, b1, n_edges);

    k_msg<<<(n_nodes + NPB - 1) / NPB, 128>>>(n_nodes, num_nbr);

    k_bn2fin<<<1, 128>>>(g2, b2, n_nodes);

    long total = (long)n_nodes * FEA;
    k_out<<<(unsigned)((total + 255) / 256), 256>>>(x, out, total);
}

// round 5
// speedup vs baseline: 1.0492x; 1.0479x over previous
#include <cuda_runtime.h>
#include <cuda_bf16.h>
#include <cstdint>

#define FEA 128      // ATOM_FEA
#define NBF 64       // NBR_FEA
#define OUTD 256     // 2*FEA
#define INDIM 320    // 2*FEA + NBF

#define MAXN 50000
#define MAXE 600000

// ---------------- device scratch (no runtime allocation allowed) ----------------
__device__ float  g_P[(size_t)MAXN * OUTD];   // X @ W[:, 0:128]^T     (gathered by nbr)
__device__ float  g_Q[(size_t)MAXN * OUTD];   // X @ W[:, 128:256]^T   (gathered by src)
__device__ float  g_U[(size_t)MAXE * OUTD];   // gated pre-BN, per edge
__device__ float  g_S[(size_t)MAXN * FEA];    // neighbor-summed messages pre-BN2
__device__ double g_s1[OUTD], g_s2[OUTD];     // BN1 sum / sumsq
__device__ double g_t1[FEA],  g_t2[FEA];      // BN2 sum / sumsq
__device__ float  g_bn1s[OUTD], g_bn1h[OUTD]; // BN1 scale/shift
__device__ float  g_bn2s[FEA],  g_bn2h[FEA];  // BN2 scale/shift
__device__ int    g_is64;

__device__ __forceinline__ long ldidx(const void* p, long i, int is64) {
    return is64 ? (long)((const long long*)p)[i] : (long)((const int*)p)[i];
}
__device__ __forceinline__ float softplusf(float z) {
    return fmaxf(z, 0.0f) + log1pf(__expf(-fabsf(z)));
}
__device__ __forceinline__ float sigmoidf(float z) {
    return 1.0f / (1.0f + __expf(-z));
}

__device__ __forceinline__ uint32_t smem_u32(const void* p) {
    uint32_t a;
    asm("{ .reg .u64 t; cvta.to.shared.u64 t, %1; cvt.u32.u64 %0, t; }" : "=r"(a) : "l"(p));
    return a;
}

// ldmatrix x4 (non-transposed)
__device__ __forceinline__ void ldm_x4(uint32_t* r, uint32_t addr) {
    asm volatile("ldmatrix.sync.aligned.m8n8.x4.shared.b16 {%0,%1,%2,%3}, [%4];"
                 : "=r"(r[0]), "=r"(r[1]), "=r"(r[2]), "=r"(r[3]) : "r"(addr));
}

// mma m16n8k16 bf16 -> f32
__device__ __forceinline__ void mma_bf16(float* c, const uint32_t* a, const uint32_t* b) {
    asm volatile(
        "mma.sync.aligned.m16n8k16.row.col.f32.bf16.bf16.f32 "
        "{%0,%1,%2,%3}, {%4,%5,%6,%7}, {%8,%9}, {%0,%1,%2,%3};"
        : "+f"(c[0]), "+f"(c[1]), "+f"(c[2]), "+f"(c[3])
        : "r"(a[0]), "r"(a[1]), "r"(a[2]), "r"(a[3]), "r"(b[0]), "r"(b[1]));
}

// split fp32 -> bf16 hi + bf16 lo
__device__ __forceinline__ void split4(float4 v, uint32_t& h01, uint32_t& h23,
                                       uint32_t& l01, uint32_t& l23) {
    __nv_bfloat16 hx = __float2bfloat16_rn(v.x);
    __nv_bfloat16 hy = __float2bfloat16_rn(v.y);
    __nv_bfloat16 hz = __float2bfloat16_rn(v.z);
    __nv_bfloat16 hw = __float2bfloat16_rn(v.w);
    __nv_bfloat16 lx = __float2bfloat16_rn(v.x - __bfloat162float(hx));
    __nv_bfloat16 ly = __float2bfloat16_rn(v.y - __bfloat162float(hy));
    __nv_bfloat16 lz = __float2bfloat16_rn(v.z - __bfloat162float(hz));
    __nv_bfloat16 lw = __float2bfloat16_rn(v.w - __bfloat162float(hw));
    __nv_bfloat162 a = __nv_bfloat162(hx, hy), b2 = __nv_bfloat162(hz, hw);
    __nv_bfloat162 c = __nv_bfloat162(lx, ly), d2 = __nv_bfloat162(lz, lw);
    h01 = *(uint32_t*)&a; h23 = *(uint32_t*)&b2;
    l01 = *(uint32_t*)&c; l23 = *(uint32_t*)&d2;
}

// ---------------- smem layout for GEMM kernels ----------------
#define PADK 72                          // 64 bf16 + 8 pad -> 144B rows (9x16B, ldmatrix conflict-free)
#define OF_AH 0
#define OF_AL (128 * PADK * 2)           // 18432
#define OF_BH (2 * 128 * PADK * 2)       // 36864
#define OF_BL (3 * 128 * PADK * 2)       // 55296
#define OF_S1 (4 * 128 * PADK * 2)       // 73728
#define OF_S2 (OF_S1 + 512)
#define SMEM_GEMM (OF_S2 + 512)          // 74752

extern __shared__ char dsm[];

// ---------------- kernel 0: zero stats + detect index dtype ----------------
__global__ void k_init(const int* __restrict__ ei32) {
    int t = threadIdx.x;
    for (int i = t; i < OUTD; i += 256) { g_s1[i] = 0.0; g_s2[i] = 0.0; }
    for (int i = t; i < FEA;  i += 256) { g_t1[i] = 0.0; g_t2[i] = 0.0; }
    if (t == 0) g_is64 = (ei32[12] == 0) ? 1 : 0;
}

// ---- shared compute: 3 terms x 4 ksteps of m16n8k16 on the staged hi/lo tiles ----
__device__ __forceinline__ void gemm_tile_3term(uint32_t sb, int m0, int n0, int lane,
                                                float acc[2][8][4]) {
    // per-lane ldmatrix source coordinates
    int aRow = (lane & 15);
    int aCol = (lane >> 4) << 3;
    int bRow = (lane & 7) + ((lane >> 4) << 3);
    int bCol = ((lane >> 3) & 1) << 3;
    #pragma unroll
    for (int term = 0; term < 3; term++) {
        uint32_t Ab = sb + ((term == 1) ? OF_AL : OF_AH);
        uint32_t Bb = sb + ((term == 2) ? OF_BL : OF_BH);
        #pragma unroll
        for (int ks = 0; ks < 4; ks++) {
            int k16 = ks * 16;
            uint32_t aF[2][4];
            #pragma unroll
            for (int i = 0; i < 2; i++)
                ldm_x4(aF[i], Ab + (uint32_t)(((m0 + i * 16 + aRow) * PADK + k16 + aCol) * 2));
            uint32_t bF[8][2];
            #pragma unroll
            for (int j2 = 0; j2 < 4; j2++) {
                uint32_t q[4];
                ldm_x4(q, Bb + (uint32_t)(((n0 + j2 * 16 + bRow) * PADK + k16 + bCol) * 2));
                bF[2*j2][0] = q[0]; bF[2*j2][1] = q[1];
                bF[2*j2+1][0] = q[2]; bF[2*j2+1][1] = q[3];
            }
            #pragma unroll
            for (int i = 0; i < 2; i++)
                #pragma unroll
                for (int j = 0; j < 8; j++)
                    mma_bf16(acc[i][j], aF[i], bF[j]);
        }
    }
}

// ================= node GEMM: (P|Q) = X @ W-half^T via mma.sync bf16 =================
// grid (ceil(N/128), 4): y&1 -> col half, y>>1 -> P(0)/Q(1) (koff applies to W ONLY)
__global__ __launch_bounds__(256, 2)
void k_nodegemm_mma(const float* __restrict__ x, const float* __restrict__ W, int n_nodes) {
    uint32_t sb = smem_u32(dsm);
    int t = threadIdx.x, wid = t >> 5, lane = t & 31;
    int wm = wid & 3, wn = wid >> 2;
    int m0 = wm * 32, n0 = wn * 64;
    int rBase = blockIdx.x * 128;
    int wb    = (blockIdx.y & 1) * 128;     // W row base (output channel base within half)
    int koff  = (blockIdx.y >> 1) * 128;    // K offset into W columns (P: 0, Q: 128)

    float acc[2][8][4] = {};

    #pragma unroll 1
    for (int kc = 0; kc < 2; kc++) {
        // stage A: x[rBase..+127][kc*64 .. +63]   (x always indexed by k, NOT koff)
        #pragma unroll
        for (int l = 0; l < 8; l++) {
            int i = t + l * 256;            // 2048 float4
            int r = i >> 4;
            int c = (i & 15) << 2;
            int node = rBase + r;
            float4 v = make_float4(0.f, 0.f, 0.f, 0.f);
            if (node < n_nodes) v = *(const float4*)(x + (size_t)node * FEA + kc * 64 + c);
            uint32_t h01, h23, l01, l23;
            split4(v, h01, h23, l01, l23);
            size_t off = (size_t)(r * PADK + c) * 2;
            *(uint2*)(dsm + OF_AH + off) = make_uint2(h01, h23);
            *(uint2*)(dsm + OF_AL + off) = make_uint2(l01, l23);
        }
        // stage B: W[wb + r][koff + kc*64 + c]
        #pragma unroll
        for (int l = 0; l < 8; l++) {
            int i = t + l * 256;
            int r = i >> 4;
            int c = (i & 15) << 2;
            float4 v = *(const float4*)(W + (size_t)(wb + r) * INDIM + koff + kc * 64 + c);
            uint32_t h01, h23, l01, l23;
            split4(v, h01, h23, l01, l23);
            size_t off = (size_t)(r * PADK + c) * 2;
            *(uint2*)(dsm + OF_BH + off) = make_uint2(h01, h23);
            *(uint2*)(dsm + OF_BL + off) = make_uint2(l01, l23);
        }
        __syncthreads();
        gemm_tile_3term(sb, m0, n0, lane, acc);
        __syncthreads();
    }

    // epilogue: scatter to P or Q
    int g = lane >> 2, tg = lane & 3;
    float* outT = (blockIdx.y >> 1) ? g_Q : g_P;
    #pragma unroll
    for (int a = 0; a < 4; a++) {
        int node = rBase + m0 + a * 8 + g;
        if (node >= n_nodes) continue;
        int i = a >> 1, h = (a & 1) * 2;
        float* orow = outT + (size_t)node * OUTD + wb;
        #pragma unroll
        for (int j = 0; j < 8; j++) {
            int c = n0 + 8 * j + 2 * tg;
            *(float2*)(orow + c) = make_float2(acc[i][j][h], acc[i][j][h + 1]);
        }
    }
}

// ================= edge GEMM + gather + U + BN1 sums =================
// grid (ceil(E/128), 2): y -> output col half (cBase = y*128)
__global__ __launch_bounds__(256, 2)
void k_edgegemm_mma(const float* __restrict__ ea, const float* __restrict__ W,
                    const float* __restrict__ bias, const void* __restrict__ eidx,
                    long n_edges) {
    uint32_t sb = smem_u32(dsm);
    int t = threadIdx.x, wid = t >> 5, lane = t & 31;
    int wm = wid & 3, wn = wid >> 2;
    int m0 = wm * 32, n0 = wn * 64;
    long eBase = (long)blockIdx.x * 128;
    int  cBase = blockIdx.y * 128;
    int  is64  = g_is64;

    float* smS1 = (float*)(dsm + OF_S1);
    float* smS2 = (float*)(dsm + OF_S2);
    if (t < 128) { smS1[t] = 0.f; smS2[t] = 0.f; }

    // stage A: ea tile [128 edges][64]
    #pragma unroll
    for (int l = 0; l < 8; l++) {
        int i = t + l * 256;
        int r = i >> 4;
        int c = (i & 15) << 2;
        long e = eBase + r;
        float4 v = make_float4(0.f, 0.f, 0.f, 0.f);
        if (e < n_edges) v = *(const float4*)(ea + e * NBF + c);
        uint32_t h01, h23, l01, l23;
        split4(v, h01, h23, l01, l23);
        size_t off = (size_t)(r * PADK + c) * 2;
        *(uint2*)(dsm + OF_AH + off) = make_uint2(h01, h23);
        *(uint2*)(dsm + OF_AL + off) = make_uint2(l01, l23);
    }
    // stage B: W3 rows cBase..cBase+127, cols 256..319
    #pragma unroll
    for (int l = 0; l < 8; l++) {
        int i = t + l * 256;
        int r = i >> 4;
        int c = (i & 15) << 2;
        float4 v = *(const float4*)(W + (size_t)(cBase + r) * INDIM + 2 * FEA + c);
        uint32_t h01, h23, l01, l23;
        split4(v, h01, h23, l01, l23);
        size_t off = (size_t)(r * PADK + c) * 2;
        *(uint2*)(dsm + OF_BH + off) = make_uint2(h01, h23);
        *(uint2*)(dsm + OF_BL + off) = make_uint2(l01, l23);
    }
    __syncthreads();

    float acc[2][8][4] = {};
    gemm_tile_3term(sb, m0, n0, lane, acc);

    // epilogue: u = acc + b + P[nbr] + Q[src]; store U; BN1 channel sums
    int g = lane >> 2, tg = lane & 3;
    bool val[4];
    const float* Pr[4];
    const float* Qr[4];
    float* Urp[4];
    #pragma unroll
    for (int a = 0; a < 4; a++) {
        long e = eBase + m0 + a * 8 + g;
        val[a] = (e < n_edges);
        long ee = val[a] ? e : 0;
        long nb = ldidx(eidx, n_edges + ee, is64);
        long sr = ldidx(eidx, ee, is64);
        Pr[a]  = g_P + (size_t)nb * OUTD;
        Qr[a]  = g_Q + (size_t)sr * OUTD;
        Urp[a] = g_U + (size_t)ee * OUTD;
    }
    #pragma unroll
    for (int j = 0; j < 8; j++) {
        int cl = n0 + 8 * j + 2 * tg;
        int c  = cBase + cl;
        float2 bv = *(const float2*)(bias + c);
        float s0 = 0.f, s1 = 0.f, q0 = 0.f, q1 = 0.f;
        #pragma unroll
        for (int a = 0; a < 4; a++) {
            if (val[a]) {
                int i = a >> 1, h = (a & 1) * 2;
                float2 p = *(const float2*)(Pr[a] + c);
                float2 q = *(const float2*)(Qr[a] + c);
                float u0 = acc[i][j][h]     + bv.x + p.x + q.x;
                float u1 = acc[i][j][h + 1] + bv.y + p.y + q.y;
                *(float2*)(Urp[a] + c) = make_float2(u0, u1);
                s0 += u0; s1 += u1; q0 += u0 * u0; q1 += u1 * u1;
            }
        }
        #pragma unroll
        for (int m = 4; m <= 16; m <<= 1) {
            s0 += __shfl_xor_sync(0xffffffffu, s0, m);
            s1 += __shfl_xor_sync(0xffffffffu, s1, m);
            q0 += __shfl_xor_sync(0xffffffffu, q0, m);
            q1 += __shfl_xor_sync(0xffffffffu, q1, m);
        }
        if (g == 0) {
            atomicAdd(&smS1[cl],     s0);
            atomicAdd(&smS1[cl + 1], s1);
            atomicAdd(&smS2[cl],     q0);
            atomicAdd(&smS2[cl + 1], q1);
        }
    }
    __syncthreads();
    if (t < 128) {
        atomicAdd(&g_s1[cBase + t], (double)smS1[t]);
        atomicAdd(&g_s2[cBase + t], (double)smS2[t]);
    }
}

// ---------------- kernel 3: BN1 finalize ----------------
__global__ void k_bn1fin(const float* __restrict__ g1, const float* __restrict__ b1,
                         long n_edges) {
    int t = threadIdx.x;  // 256
    double inv = 1.0 / (double)n_edges;
    double m   = g_s1[t] * inv;
    double var = g_s2[t] * inv - m * m;
    float rs = (float)rsqrt(var + 1e-5);
    float sc = g1[t] * rs;
    g_bn1s[t] = sc;
    g_bn1h[t] = b1[t] - (float)m * sc;
}

// ---------------- kernel 4: gate+softplus, 12-neighbor sum, BN2 sums ----------------
#define NPB 32
__global__ __launch_bounds__(128)
void k_msg(int n_nodes, int num_nbr) {
    int tx = threadIdx.x;  // channel 0..127
    float s1f = g_bn1s[tx],       h1f = g_bn1h[tx];
    float s1c = g_bn1s[128 + tx], h1c = g_bn1h[128 + tx];
    float tsum = 0.f, tsq = 0.f;
    int n0 = blockIdx.x * NPB;
    for (int nn = 0; nn < NPB; nn++) {
        int node = n0 + nn;
        if (node >= n_nodes) break;
        float s = 0.f;
        long eb = (long)node * num_nbr;
        for (int j = 0; j < num_nbr; j++) {
            const float* Ur = g_U + (size_t)(eb + j) * OUTD;
            float fz = fmaf(s1f, Ur[tx],       h1f);
            float cz = fmaf(s1c, Ur[128 + tx], h1c);
            s += sigmoidf(fz) * softplusf(cz);
        }
        g_S[(size_t)node * FEA + tx] = s;
        tsum += s; tsq += s * s;
    }
    atomicAdd(&g_t1[tx], (double)tsum);
    atomicAdd(&g_t2[tx], (double)tsq);
}

// ---------------- kernel 5: BN2 finalize ----------------
__global__ void k_bn2fin(const float* __restrict__ g2, const float* __restrict__ b2,
                         int n_nodes) {
    int t = threadIdx.x;  // 128
    double inv = 1.0 / (double)n_nodes;
    double m   = g_t1[t] * inv;
    double var = g_t2[t] * inv - m * m;
    float rs = (float)rsqrt(var + 1e-5);
    float sc = g2[t] * rs;
    g_bn2s[t] = sc;
    g_bn2h[t] = b2[t] - (float)m * sc;
}

// ---------------- kernel 6: output = softplus(x + bn2(S)) ----------------
__global__ void k_out(const float* __restrict__ x, float* __restrict__ out, long total) {
    long i = (long)blockIdx.x * blockDim.x + threadIdx.x;
    if (i >= total) return;
    int c = (int)(i & (FEA - 1));
    float v = x[i] + g_bn2s[c] * g_S[i] + g_bn2h[c];
    out[i] = softplusf(v);
}

// ---------------- launch ----------------
extern "C" void kernel_launch(void* const* d_in, const int* in_sizes, int n_in,
                              void* d_out, int out_size) {
    const float* x    = (const float*)d_in[0];
    const void*  eidx = d_in[1];
    const float* ea   = (const float*)d_in[2];
    const float* W    = (const float*)d_in[3];
    const float* b    = (const float*)d_in[4];
    const float* g1   = (const float*)d_in[5];
    const float* b1   = (const float*)d_in[6];
    const float* g2   = (const float*)d_in[7];
    const float* b2   = (const float*)d_in[8];
    float* out = (float*)d_out;

    int  n_nodes = in_sizes[0] / FEA;
    long n_edges = (long)in_sizes[2] / NBF;
    int  num_nbr = (int)(n_edges / n_nodes);

    cudaFuncSetAttribute(k_nodegemm_mma, cudaFuncAttributeMaxDynamicSharedMemorySize, SMEM_GEMM);
    cudaFuncSetAttribute(k_edgegemm_mma, cudaFuncAttributeMaxDynamicSharedMemorySize, SMEM_GEMM);

    k_init<<<1, 256>>>((const int*)eidx);

    dim3 gridN((n_nodes + 127) / 128, 4);
    k_nodegemm_mma<<<gridN, 256, SMEM_GEMM>>>(x, W, n_nodes);

    dim3 gridE((unsigned)((n_edges + 127) / 128), 2);
    k_edgegemm_mma<<<gridE, 256, SMEM_GEMM>>>(ea, W, b, eidx, n_edges);

    k_bn1fin<<<1, 256>>>(g1, b1, n_edges);

    k_msg<<<(n_nodes + NPB - 1) / NPB, 128>>>(n_nodes, num_nbr);

    k_bn2fin<<<1, 128>>>(g2, b2, n_nodes);

    long total = (long)n_nodes * FEA;
    k_out<<<(unsigned)((total + 255) / 256), 256>>>(x, out, total);
}

// round 6
// speedup vs baseline: 1.2373x; 1.1792x over previous
#include <cuda_runtime.h>
#include <cuda_bf16.h>
#include <cuda_fp16.h>
#include <cstdint>

#define FEA 128      // ATOM_FEA
#define NBF 64       // NBR_FEA
#define OUTD 256     // 2*FEA
#define INDIM 320    // 2*FEA + NBF

#define MAXN 50000
#define MAXE 600000

// ---------------- device scratch (no runtime allocation allowed) ----------------
__device__ float  g_P[(size_t)MAXN * OUTD];   // X @ W[:, 0:128]^T     (gathered by nbr)
__device__ float  g_Q[(size_t)MAXN * OUTD];   // X @ W[:, 128:256]^T   (gathered by src)
__device__ __half g_U16[(size_t)MAXE * OUTD]; // gated pre-BN, per edge (fp16)
__device__ float  g_S[(size_t)MAXN * FEA];    // neighbor-summed messages pre-BN2
__device__ double g_s1[OUTD], g_s2[OUTD];     // BN1 sum / sumsq
__device__ double g_t1[FEA],  g_t2[FEA];      // BN2 sum / sumsq
__device__ float  g_bn1s[OUTD], g_bn1h[OUTD]; // BN1 scale/shift
__device__ float  g_bn2s[FEA],  g_bn2h[FEA];  // BN2 scale/shift
__device__ int    g_is64;

__device__ __forceinline__ long ldidx(const void* p, long i, int is64) {
    return is64 ? (long)((const long long*)p)[i] : (long)((const int*)p)[i];
}
__device__ __forceinline__ float softplusf(float z) {
    return fmaxf(z, 0.0f) + log1pf(__expf(-fabsf(z)));
}
__device__ __forceinline__ float sigmoidf(float z) {
    return 1.0f / (1.0f + __expf(-z));
}

__device__ __forceinline__ uint32_t smem_u32(const void* p) {
    uint32_t a;
    asm("{ .reg .u64 t; cvta.to.shared.u64 t, %1; cvt.u32.u64 %0, t; }" : "=r"(a) : "l"(p));
    return a;
}

// ldmatrix x4 (non-transposed)
__device__ __forceinline__ void ldm_x4(uint32_t* r, uint32_t addr) {
    asm volatile("ldmatrix.sync.aligned.m8n8.x4.shared.b16 {%0,%1,%2,%3}, [%4];"
                 : "=r"(r[0]), "=r"(r[1]), "=r"(r[2]), "=r"(r[3]) : "r"(addr));
}

// mma m16n8k16 bf16 -> f32
__device__ __forceinline__ void mma_bf16(float* c, const uint32_t* a, const uint32_t* b) {
    asm volatile(
        "mma.sync.aligned.m16n8k16.row.col.f32.bf16.bf16.f32 "
        "{%0,%1,%2,%3}, {%4,%5,%6,%7}, {%8,%9}, {%0,%1,%2,%3};"
        : "+f"(c[0]), "+f"(c[1]), "+f"(c[2]), "+f"(c[3])
        : "r"(a[0]), "r"(a[1]), "r"(a[2]), "r"(a[3]), "r"(b[0]), "r"(b[1]));
}

// split fp32 -> bf16 hi + bf16 lo
__device__ __forceinline__ void split4(float4 v, uint32_t& h01, uint32_t& h23,
                                       uint32_t& l01, uint32_t& l23) {
    __nv_bfloat16 hx = __float2bfloat16_rn(v.x);
    __nv_bfloat16 hy = __float2bfloat16_rn(v.y);
    __nv_bfloat16 hz = __float2bfloat16_rn(v.z);
    __nv_bfloat16 hw = __float2bfloat16_rn(v.w);
    __nv_bfloat16 lx = __float2bfloat16_rn(v.x - __bfloat162float(hx));
    __nv_bfloat16 ly = __float2bfloat16_rn(v.y - __bfloat162float(hy));
    __nv_bfloat16 lz = __float2bfloat16_rn(v.z - __bfloat162float(hz));
    __nv_bfloat16 lw = __float2bfloat16_rn(v.w - __bfloat162float(hw));
    __nv_bfloat162 a = __nv_bfloat162(hx, hy), b2 = __nv_bfloat162(hz, hw);
    __nv_bfloat162 c = __nv_bfloat162(lx, ly), d2 = __nv_bfloat162(lz, lw);
    h01 = *(uint32_t*)&a; h23 = *(uint32_t*)&b2;
    l01 = *(uint32_t*)&c; l23 = *(uint32_t*)&d2;
}

// ---------------- smem layout for GEMM kernels ----------------
#define PADK 72                          // 64 bf16 + 8 pad -> 144B rows, ldmatrix conflict-free
#define OF_AH 0
#define OF_AL (128 * PADK * 2)           // 18432
#define OF_BH (2 * 128 * PADK * 2)       // 36864
#define OF_BL (3 * 128 * PADK * 2)       // 55296
#define OF_S1 (4 * 128 * PADK * 2)       // 73728  (beyond u-tile 128*132*4=67584)
#define OF_S2 (OF_S1 + 512)
#define SMEM_GEMM (OF_S2 + 512)          // 74752
#define UTS 132                          // u-tile row stride (floats)

extern __shared__ char dsm[];

// ---------------- kernel 0: zero stats + detect index dtype ----------------
__global__ void k_init(const int* __restrict__ ei32) {
    int t = threadIdx.x;
    for (int i = t; i < OUTD; i += 256) { g_s1[i] = 0.0; g_s2[i] = 0.0; }
    for (int i = t; i < FEA;  i += 256) { g_t1[i] = 0.0; g_t2[i] = 0.0; }
    if (t == 0) g_is64 = (ei32[12] == 0) ? 1 : 0;
}

// ---- shared compute: 3 terms x 4 ksteps of m16n8k16 on the staged hi/lo tiles ----
__device__ __forceinline__ void gemm_tile_3term(uint32_t sb, int m0, int n0, int lane,
                                                float acc[2][8][4]) {
    int aRow = (lane & 15);
    int aCol = (lane >> 4) << 3;
    int bRow = (lane & 7) + ((lane >> 4) << 3);
    int bCol = ((lane >> 3) & 1) << 3;
    #pragma unroll
    for (int term = 0; term < 3; term++) {
        uint32_t Ab = sb + ((term == 1) ? OF_AL : OF_AH);
        uint32_t Bb = sb + ((term == 2) ? OF_BL : OF_BH);
        #pragma unroll
        for (int ks = 0; ks < 4; ks++) {
            int k16 = ks * 16;
            uint32_t aF[2][4];
            #pragma unroll
            for (int i = 0; i < 2; i++)
                ldm_x4(aF[i], Ab + (uint32_t)(((m0 + i * 16 + aRow) * PADK + k16 + aCol) * 2));
            uint32_t bF[8][2];
            #pragma unroll
            for (int j2 = 0; j2 < 4; j2++) {
                uint32_t q[4];
                ldm_x4(q, Bb + (uint32_t)(((n0 + j2 * 16 + bRow) * PADK + k16 + bCol) * 2));
                bF[2*j2][0] = q[0]; bF[2*j2][1] = q[1];
                bF[2*j2+1][0] = q[2]; bF[2*j2+1][1] = q[3];
            }
            #pragma unroll
            for (int i = 0; i < 2; i++)
                #pragma unroll
                for (int j = 0; j < 8; j++)
                    mma_bf16(acc[i][j], aF[i], bF[j]);
        }
    }
}

// ================= node GEMM: (P|Q) = X @ W-half^T via mma.sync bf16 =================
// grid (ceil(N/128), 4): y&1 -> col half, y>>1 -> P(0)/Q(1) (koff applies to W ONLY)
__global__ __launch_bounds__(256, 2)
void k_nodegemm_mma(const float* __restrict__ x, const float* __restrict__ W, int n_nodes) {
    uint32_t sb = smem_u32(dsm);
    int t = threadIdx.x, wid = t >> 5, lane = t & 31;
    int wm = wid & 3, wn = wid >> 2;
    int m0 = wm * 32, n0 = wn * 64;
    int rBase = blockIdx.x * 128;
    int wb    = (blockIdx.y & 1) * 128;
    int koff  = (blockIdx.y >> 1) * 128;

    float acc[2][8][4] = {};

    #pragma unroll 1
    for (int kc = 0; kc < 2; kc++) {
        #pragma unroll
        for (int l = 0; l < 8; l++) {
            int i = t + l * 256;
            int r = i >> 4;
            int c = (i & 15) << 2;
            int node = rBase + r;
            float4 v = make_float4(0.f, 0.f, 0.f, 0.f);
            if (node < n_nodes) v = *(const float4*)(x + (size_t)node * FEA + kc * 64 + c);
            uint32_t h01, h23, l01, l23;
            split4(v, h01, h23, l01, l23);
            size_t off = (size_t)(r * PADK + c) * 2;
            *(uint2*)(dsm + OF_AH + off) = make_uint2(h01, h23);
            *(uint2*)(dsm + OF_AL + off) = make_uint2(l01, l23);
        }
        #pragma unroll
        for (int l = 0; l < 8; l++) {
            int i = t + l * 256;
            int r = i >> 4;
            int c = (i & 15) << 2;
            float4 v = *(const float4*)(W + (size_t)(wb + r) * INDIM + koff + kc * 64 + c);
            uint32_t h01, h23, l01, l23;
            split4(v, h01, h23, l01, l23);
            size_t off = (size_t)(r * PADK + c) * 2;
            *(uint2*)(dsm + OF_BH + off) = make_uint2(h01, h23);
            *(uint2*)(dsm + OF_BL + off) = make_uint2(l01, l23);
        }
        __syncthreads();
        gemm_tile_3term(sb, m0, n0, lane, acc);
        __syncthreads();
    }

    int g = lane >> 2, tg = lane & 3;
    float* outT = (blockIdx.y >> 1) ? g_Q : g_P;
    #pragma unroll
    for (int a = 0; a < 4; a++) {
        int node = rBase + m0 + a * 8 + g;
        if (node >= n_nodes) continue;
        int i = a >> 1, h = (a & 1) * 2;
        float* orow = outT + (size_t)node * OUTD + wb;
        #pragma unroll
        for (int j = 0; j < 8; j++) {
            int c = n0 + 8 * j + 2 * tg;
            *(float2*)(orow + c) = make_float2(acc[i][j][h], acc[i][j][h + 1]);
        }
    }
}

// ================= edge GEMM + gather + U(fp16) + BN1 sums =================
// grid (ceil(E/128), 2): y -> output col half (cBase = y*128)
__global__ __launch_bounds__(256, 2)
void k_edgegemm_mma(const float* __restrict__ ea, const float* __restrict__ W,
                    const float* __restrict__ bias, const void* __restrict__ eidx,
                    long n_edges) {
    uint32_t sb = smem_u32(dsm);
    int t = threadIdx.x, wid = t >> 5, lane = t & 31;
    int wm = wid & 3, wn = wid >> 2;
    int m0 = wm * 32, n0 = wn * 64;
    long eBase = (long)blockIdx.x * 128;
    int  cBase = blockIdx.y * 128;
    int  is64  = g_is64;

    float* smS1 = (float*)(dsm + OF_S1);
    float* smS2 = (float*)(dsm + OF_S2);
    if (t < 128) { smS1[t] = 0.f; smS2[t] = 0.f; }

    // stage A: ea tile [128 edges][64]
    #pragma unroll
    for (int l = 0; l < 8; l++) {
        int i = t + l * 256;
        int r = i >> 4;
        int c = (i & 15) << 2;
        long e = eBase + r;
        float4 v = make_float4(0.f, 0.f, 0.f, 0.f);
        if (e < n_edges) v = *(const float4*)(ea + e * NBF + c);
        uint32_t h01, h23, l01, l23;
        split4(v, h01, h23, l01, l23);
        size_t off = (size_t)(r * PADK + c) * 2;
        *(uint2*)(dsm + OF_AH + off) = make_uint2(h01, h23);
        *(uint2*)(dsm + OF_AL + off) = make_uint2(l01, l23);
    }
    // stage B: W3 rows cBase..cBase+127, cols 256..319
    #pragma unroll
    for (int l = 0; l < 8; l++) {
        int i = t + l * 256;
        int r = i >> 4;
        int c = (i & 15) << 2;
        float4 v = *(const float4*)(W + (size_t)(cBase + r) * INDIM + 2 * FEA + c);
        uint32_t h01, h23, l01, l23;
        split4(v, h01, h23, l01, l23);
        size_t off = (size_t)(r * PADK + c) * 2;
        *(uint2*)(dsm + OF_BH + off) = make_uint2(h01, h23);
        *(uint2*)(dsm + OF_BL + off) = make_uint2(l01, l23);
    }
    __syncthreads();

    float acc[2][8][4] = {};
    gemm_tile_3term(sb, m0, n0, lane, acc);
    __syncthreads();                         // staging reads done; safe to alias

    // dump fragments to u-tile [128][UTS]
    float* ut = (float*)dsm;
    int g = lane >> 2, tg = lane & 3;
    #pragma unroll
    for (int a = 0; a < 4; a++) {
        int r = m0 + a * 8 + g;
        int i = a >> 1, h = (a & 1) * 2;
        #pragma unroll
        for (int j = 0; j < 8; j++)
            *(float2*)(ut + r * UTS + n0 + 8 * j + 2 * tg) =
                make_float2(acc[i][j][h], acc[i][j][h + 1]);
    }
    __syncthreads();

    // per-warp epilogue over 16 whole edge rows (coalesced)
    // lane-parallel index prefetch for the warp's 16 edges
    long myE = eBase + wid * 16 + (lane & 15);
    long nb_l = 0, sr_l = 0;
    if (myE < n_edges) {
        nb_l = ldidx(eidx, n_edges + myE, is64);
        sr_l = ldidx(eidx, myE, is64);
    }
    int c4 = lane * 4;                        // local channel 0..124
    int c  = cBase + c4;
    float4 bv = *(const float4*)(bias + c4 + cBase);
    float s1v[4] = {}, s2v[4] = {};

    #pragma unroll 4
    for (int rr = 0; rr < 16; rr++) {
        int r = wid * 16 + rr;
        long e = eBase + r;
        if (e >= n_edges) break;
        long nb = __shfl_sync(0xffffffffu, nb_l, rr);
        long sr = __shfl_sync(0xffffffffu, sr_l, rr);
        float4 u = *(const float4*)(ut + r * UTS + c4);
        float4 p = *(const float4*)(g_P + (size_t)nb * OUTD + c);
        float4 q = *(const float4*)(g_Q + (size_t)sr * OUTD + c);
        u.x += bv.x + p.x + q.x;
        u.y += bv.y + p.y + q.y;
        u.z += bv.z + p.z + q.z;
        u.w += bv.w + p.w + q.w;
        __half2 h0 = __floats2half2_rn(u.x, u.y);
        __half2 h1 = __floats2half2_rn(u.z, u.w);
        *(uint2*)(g_U16 + (size_t)e * OUTD + c) =
            make_uint2(*(uint32_t*)&h0, *(uint32_t*)&h1);
        s1v[0] += u.x; s1v[1] += u.y; s1v[2] += u.z; s1v[3] += u.w;
        s2v[0] += u.x * u.x; s2v[1] += u.y * u.y; s2v[2] += u.z * u.z; s2v[3] += u.w * u.w;
    }
    #pragma unroll
    for (int k = 0; k < 4; k++) {
        atomicAdd(&smS1[c4 + k], s1v[k]);
        atomicAdd(&smS2[c4 + k], s2v[k]);
    }
    __syncthreads();
    if (t < 128) {
        atomicAdd(&g_s1[cBase + t], (double)smS1[t]);
        atomicAdd(&g_s2[cBase + t], (double)smS2[t]);
    }
}

// ---------------- kernel 3: BN1 finalize ----------------
__global__ void k_bn1fin(const float* __restrict__ g1, const float* __restrict__ b1,
                         long n_edges) {
    int t = threadIdx.x;  // 256
    double inv = 1.0 / (double)n_edges;
    double m   = g_s1[t] * inv;
    double var = g_s2[t] * inv - m * m;
    float rs = (float)rsqrt(var + 1e-5);
    float sc = g1[t] * rs;
    g_bn1s[t] = sc;
    g_bn1h[t] = b1[t] - (float)m * sc;
}

// ---------------- kernel 4: gate+softplus, 12-neighbor sum, BN2 sums ----------------
#define NPB 16
__global__ __launch_bounds__(128)
void k_msg(int n_nodes, int num_nbr) {
    int tx = threadIdx.x;  // channel 0..127
    float s1f = g_bn1s[tx],       h1f = g_bn1h[tx];
    float s1c = g_bn1s[128 + tx], h1c = g_bn1h[128 + tx];
    float tsum = 0.f, tsq = 0.f;
    int n0 = blockIdx.x * NPB;
    for (int nn = 0; nn < NPB; nn++) {
        int node = n0 + nn;
        if (node >= n_nodes) break;
        float s = 0.f;
        long eb = (long)node * num_nbr;
        for (int j = 0; j < num_nbr; j++) {
            const __half* Ur = g_U16 + (size_t)(eb + j) * OUTD;
            float fz = fmaf(s1f, __half2float(Ur[tx]),       h1f);
            float cz = fmaf(s1c, __half2float(Ur[128 + tx]), h1c);
            s += sigmoidf(fz) * softplusf(cz);
        }
        g_S[(size_t)node * FEA + tx] = s;
        tsum += s; tsq += s * s;
    }
    atomicAdd(&g_t1[tx], (double)tsum);
    atomicAdd(&g_t2[tx], (double)tsq);
}

// ---------------- kernel 5: BN2 finalize ----------------
__global__ void k_bn2fin(const float* __restrict__ g2, const float* __restrict__ b2,
                         int n_nodes) {
    int t = threadIdx.x;  // 128
    double inv = 1.0 / (double)n_nodes;
    double m   = g_t1[t] * inv;
    double var = g_t2[t] * inv - m * m;
    float rs = (float)rsqrt(var + 1e-5);
    float sc = g2[t] * rs;
    g_bn2s[t] = sc;
    g_bn2h[t] = b2[t] - (float)m * sc;
}

// ---------------- kernel 6: output = softplus(x + bn2(S)) ----------------
__global__ void k_out(const float* __restrict__ x, float* __restrict__ out, long total) {
    long i = (long)blockIdx.x * blockDim.x + threadIdx.x;
    if (i >= total) return;
    int c = (int)(i & (FEA - 1));
    float v = x[i] + g_bn2s[c] * g_S[i] + g_bn2h[c];
    out[i] = softplusf(v);
}

// ---------------- launch ----------------
extern "C" void kernel_launch(void* const* d_in, const int* in_sizes, int n_in,
                              void* d_out, int out_size) {
    const float* x    = (const float*)d_in[0];
    const void*  eidx = d_in[1];
    const float* ea   = (const float*)d_in[2];
    const float* W    = (const float*)d_in[3];
    const float* b    = (const float*)d_in[4];
    const float* g1   = (const float*)d_in[5];
    const float* b1   = (const float*)d_in[6];
    const float* g2   = (const float*)d_in[7];
    const float* b2   = (const float*)d_in[8];
    float* out = (float*)d_out;

    int  n_nodes = in_sizes[0] / FEA;
    long n_edges = (long)in_sizes[2] / NBF;
    int  num_nbr = (int)(n_edges / n_nodes);

    cudaFuncSetAttribute(k_nodegemm_mma, cudaFuncAttributeMaxDynamicSharedMemorySize, SMEM_GEMM);
    cudaFuncSetAttribute(k_edgegemm_mma, cudaFuncAttributeMaxDynamicSharedMemorySize, SMEM_GEMM);

    k_init<<<1, 256>>>((const int*)eidx);

    dim3 gridN((n_nodes + 127) / 128, 4);
    k_nodegemm_mma<<<gridN, 256, SMEM_GEMM>>>(x, W, n_nodes);

    dim3 gridE((unsigned)((n_edges + 127) / 128), 2);
    k_edgegemm_mma<<<gridE, 256, SMEM_GEMM>>>(ea, W, b, eidx, n_edges);

    k_bn1fin<<<1, 256>>>(g1, b1, n_edges);

    k_msg<<<(n_nodes + NPB - 1) / NPB, 128>>>(n_nodes, num_nbr);

    k_bn2fin<<<1, 128>>>(g2, b2, n_nodes);

    long total = (long)n_nodes * FEA;
    k_out<<<(unsigned)((total + 255) / 256), 256>>>(x, out, total);
}